// round 1
// baseline (speedup 1.0000x reference)
#include <cuda_runtime.h>
#include <math.h>

#define BATCH 4
#define T_IN 1920
#define E_IN 512
#define C1 128
#define T1 640
#define C2 1024
#define T2 128

// Scratch (device globals; no allocations allowed)
__device__ float g_h1[5 * T1 * C1];          // conv1+ln1+silu output: slots 0..3 = values batches, 4 = symbols
__device__ float g_vp[BATCH * T2 * C2];      // values_projected
__device__ float g_sp[T2 * C2];              // symbol_projected (batch-invariant)
__device__ float g_S[BATCH * T2 * T2];       // similarity S[b][j][i]

__device__ __forceinline__ float silu_f(float y) {
    return y / (1.0f + expf(-y));
}

__device__ __forceinline__ float sgnp(float a, float b) {
    float sa = (a > 0.f) ? 1.f : ((a < 0.f) ? -1.f : 0.f);
    float sb = (b > 0.f) ? 1.f : ((b < 0.f) ? -1.f : 0.f);
    return sa * sb;
}

// ---------------------------------------------------------------------------
// Kernel A: conv1 (stride 3, window 5, pad 1/1) + layernorm(128) + silu
// 400 blocks x 128 threads. TS1=8 output timesteps per block.
// Channel chunking (E split into 2 halves of 256) keeps static smem < 48KB.
// ---------------------------------------------------------------------------
#define TS1 8
#define ECH 256

__global__ void conv1_ln_silu(const float* __restrict__ values,
                              const float* __restrict__ symbols,
                              const float* __restrict__ w,
                              const float* __restrict__ bias,
                              const float* __restrict__ lng,
                              const float* __restrict__ lnb) {
    __shared__ float xs[26 * ECH];   // 26 input rows x 256 channels = 26.6KB
    __shared__ float red[2][4];

    int blk = blockIdx.x;
    int src, t0;
    if (blk < 320) { src = blk / 80; t0 = (blk % 80) * TS1; }
    else           { src = 4;        t0 = (blk - 320) * TS1; }
    const float* x = (src < 4) ? (values + (size_t)src * T_IN * E_IN) : symbols;

    int base_row = t0 * 3 - 1;     // pad-left 1
    int o = threadIdx.x;

    float acc[TS1];
    float bv = bias[o];
#pragma unroll
    for (int j = 0; j < TS1; j++) acc[j] = bv;

    for (int cc = 0; cc < E_IN; cc += ECH) {
        __syncthreads();
        // stage 26 rows x 256 ch (float4)
        for (int idx = threadIdx.x; idx < 26 * (ECH / 4); idx += blockDim.x) {
            int r  = idx / (ECH / 4);
            int c4 = idx % (ECH / 4);
            int gr = base_row + r;
            float4 v = make_float4(0.f, 0.f, 0.f, 0.f);
            if (gr >= 0 && gr < T_IN)
                v = ((const float4*)(x + (size_t)gr * E_IN + cc))[c4];
            ((float4*)xs)[idx] = v;
        }
        __syncthreads();

        for (int k = 0; k < 5; k++) {
            const float* wk = w + ((size_t)k * E_IN + cc) * C1 + o;
#pragma unroll 2
            for (int c = 0; c < ECH; c += 4) {
                float w0 = wk[(c + 0) * C1];
                float w1 = wk[(c + 1) * C1];
                float w2 = wk[(c + 2) * C1];
                float w3 = wk[(c + 3) * C1];
#pragma unroll
                for (int j = 0; j < TS1; j++) {
                    const float4 xv = *(const float4*)&xs[(3 * j + k) * ECH + c];
                    acc[j] += xv.x * w0;
                    acc[j] += xv.y * w1;
                    acc[j] += xv.z * w2;
                    acc[j] += xv.w * w3;
                }
            }
        }
    }

    // layernorm over the 128 channels (== blockDim) + silu
    float gg = lng[o], bb = lnb[o];
    int lane = threadIdx.x & 31, wid = threadIdx.x >> 5;
    __syncthreads();
    for (int j = 0; j < TS1; j++) {
        float v = acc[j];
        float s = v, s2 = v * v;
#pragma unroll
        for (int off = 16; off; off >>= 1) {
            s  += __shfl_xor_sync(0xffffffffu, s,  off);
            s2 += __shfl_xor_sync(0xffffffffu, s2, off);
        }
        if (lane == 0) { red[0][wid] = s; red[1][wid] = s2; }
        __syncthreads();
        float sum   = red[0][0] + red[0][1] + red[0][2] + red[0][3];
        float sumsq = red[1][0] + red[1][1] + red[1][2] + red[1][3];
        __syncthreads();
        float m   = sum * (1.0f / C1);
        float var = sumsq * (1.0f / C1) - m * m;
        float y   = (v - m) * rsqrtf(var + 1e-3f) * gg + bb;
        g_h1[((size_t)src * T1 + (t0 + j)) * C1 + o] = silu_f(y);
    }
}

// ---------------------------------------------------------------------------
// Kernel B: conv2 (stride 5, window 3, no pad) + layernorm(1024) + silu
// 160 blocks x 256 threads. TS2=4 output rows/block; thread owns 4 channels.
// Writes g_vp (+ copy into d_out second half) and g_sp.
// ---------------------------------------------------------------------------
#define TS2 4

__global__ void conv2_ln_silu(const float* __restrict__ w,
                              const float* __restrict__ bias,
                              const float* __restrict__ lng,
                              const float* __restrict__ lnb,
                              float* __restrict__ out_vp_copy) {
    __shared__ float xs[18 * C1];   // 9KB
    __shared__ float red[2][8];

    int blk = blockIdx.x;
    int src, t0;
    if (blk < 128) { src = blk / 32; t0 = (blk % 32) * TS2; }
    else           { src = 4;        t0 = (blk - 128) * TS2; }
    const float* x = g_h1 + (size_t)src * T1 * C1;
    int base_row = t0 * 5;

    for (int idx = threadIdx.x; idx < 18 * (C1 / 4); idx += blockDim.x) {
        int r = idx / (C1 / 4), c4 = idx % (C1 / 4);
        ((float4*)xs)[idx] = ((const float4*)(x + (size_t)(base_row + r) * C1))[c4];
    }
    __syncthreads();

    int ob = threadIdx.x;   // 0..255; channels ob, ob+256, ob+512, ob+768
    float acc[TS2][4];
#pragma unroll
    for (int j = 0; j < TS2; j++)
#pragma unroll
        for (int q = 0; q < 4; q++) acc[j][q] = bias[ob + q * 256];

    for (int k = 0; k < 3; k++) {
#pragma unroll 2
        for (int c = 0; c < C1; c++) {
            const float* wp = w + ((size_t)(k * C1 + c)) * C2 + ob;
            float w0 = wp[0], w1 = wp[256], w2v = wp[512], w3 = wp[768];
            float xv[TS2];
#pragma unroll
            for (int j = 0; j < TS2; j++) xv[j] = xs[(5 * j + k) * C1 + c];
#pragma unroll
            for (int j = 0; j < TS2; j++) {
                acc[j][0] += xv[j] * w0;
                acc[j][1] += xv[j] * w1;
                acc[j][2] += xv[j] * w2v;
                acc[j][3] += xv[j] * w3;
            }
        }
    }

    int lane = threadIdx.x & 31, wid = threadIdx.x >> 5;
    for (int j = 0; j < TS2; j++) {
        float s = 0.f, s2 = 0.f;
#pragma unroll
        for (int q = 0; q < 4; q++) { s += acc[j][q]; s2 += acc[j][q] * acc[j][q]; }
#pragma unroll
        for (int off = 16; off; off >>= 1) {
            s  += __shfl_xor_sync(0xffffffffu, s,  off);
            s2 += __shfl_xor_sync(0xffffffffu, s2, off);
        }
        if (lane == 0) { red[0][wid] = s; red[1][wid] = s2; }
        __syncthreads();
        float sum = 0.f, sumsq = 0.f;
#pragma unroll
        for (int q = 0; q < 8; q++) { sum += red[0][q]; sumsq += red[1][q]; }
        __syncthreads();
        float m   = sum * (1.0f / C2);
        float var = sumsq * (1.0f / C2) - m * m;
        float rs  = rsqrtf(var + 1e-3f);
#pragma unroll
        for (int q = 0; q < 4; q++) {
            int o = ob + q * 256;
            float y = (acc[j][q] - m) * rs * lng[o] + lnb[o];
            float r = silu_f(y);
            if (src < 4) {
                size_t idx = ((size_t)(src * T2 + t0 + j)) * C2 + o;
                g_vp[idx] = r;
                out_vp_copy[idx] = r;       // second half of output tuple
            } else {
                g_sp[(size_t)(t0 + j) * C2 + o] = r;
            }
        }
    }
}

// ---------------------------------------------------------------------------
// Kernel C: S[b,j,i] = mean_d sign(vp[b,i,d]) * sign(vp[b,i,d] + sp[j,d])
// 64 blocks (b,jt,it) x 256 threads; 32x32 tile per block, 2x2 per thread.
// SMEM padded to 129 to avoid stride-1024 bank conflicts.
// ---------------------------------------------------------------------------
__global__ void sim_kernel() {
    __shared__ float vps[32][129];
    __shared__ float sps[32][129];

    int blk = blockIdx.x;
    int b  = blk >> 4;
    int jt = (blk >> 2) & 3;
    int it = blk & 3;
    int i0 = it * 32, j0 = jt * 32;
    int t  = threadIdx.x;
    int ti = (t & 15) * 2;
    int tj = (t >> 4) * 2;

    float a00 = 0.f, a01 = 0.f, a10 = 0.f, a11 = 0.f;  // a[i_off][j_off]

    for (int d0 = 0; d0 < C2; d0 += 128) {
        __syncthreads();
        for (int e = t; e < 32 * 128; e += 256) {
            int r = e >> 7, c = e & 127;
            vps[r][c] = g_vp[((size_t)(b * T2 + i0 + r)) * C2 + d0 + c];
            sps[r][c] = g_sp[(size_t)(j0 + r) * C2 + d0 + c];
        }
        __syncthreads();
#pragma unroll 4
        for (int d = 0; d < 128; d++) {
            float v0 = vps[ti][d],     v1 = vps[ti + 1][d];
            float s0 = sps[tj][d],     s1 = sps[tj + 1][d];
            a00 += sgnp(v0, v0 + s0);
            a01 += sgnp(v0, v0 + s1);
            a10 += sgnp(v1, v1 + s0);
            a11 += sgnp(v1, v1 + s1);
        }
    }

    const float inv = 1.0f / 1024.0f;
    size_t baseS = ((size_t)b * T2 + (j0 + tj)) * T2 + (i0 + ti);
    g_S[baseS]          = a00 * inv;   // (j=tj,   i=ti)
    g_S[baseS + 1]      = a10 * inv;   // (j=tj,   i=ti+1)
    g_S[baseS + T2]     = a01 * inv;   // (j=tj+1, i=ti)
    g_S[baseS + T2 + 1] = a11 * inv;   // (j=tj+1, i=ti+1)
}

// ---------------------------------------------------------------------------
// Kernel D: softmax over i + attn = scores @ vp + O = silu(attn * sp)
// 128 blocks (b, j-group of 4) x 256 threads (4 d's each, float4).
// ---------------------------------------------------------------------------
__global__ void attn_kernel(float* __restrict__ out) {
    __shared__ float sc[4][T2];

    int blk = blockIdx.x;
    int b  = blk >> 5;
    int j0 = (blk & 31) * 4;
    int t = threadIdx.x, lane = t & 31, wid = t >> 5;

    if (wid < 4) {
        int j = j0 + wid;
        const float* Sr = g_S + ((size_t)b * T2 + j) * T2;
        float v[4];
#pragma unroll
        for (int u = 0; u < 4; u++) v[u] = Sr[lane + 32 * u];
        float mx = fmaxf(fmaxf(v[0], v[1]), fmaxf(v[2], v[3]));
#pragma unroll
        for (int off = 16; off; off >>= 1)
            mx = fmaxf(mx, __shfl_xor_sync(0xffffffffu, mx, off));
        float sum = 0.f;
#pragma unroll
        for (int u = 0; u < 4; u++) { v[u] = expf(v[u] - mx); sum += v[u]; }
#pragma unroll
        for (int off = 16; off; off >>= 1)
            sum += __shfl_xor_sync(0xffffffffu, sum, off);
        float invs = 1.0f / sum;
#pragma unroll
        for (int u = 0; u < 4; u++) sc[wid][lane + 32 * u] = v[u] * invs;
    }
    __syncthreads();

    int d = t * 4;
    float4 acc[4];
#pragma unroll
    for (int jl = 0; jl < 4; jl++) acc[jl] = make_float4(0.f, 0.f, 0.f, 0.f);

    const float* vpb = g_vp + (size_t)b * T2 * C2;
    for (int i = 0; i < T2; i++) {
        float4 v = *(const float4*)(vpb + (size_t)i * C2 + d);
#pragma unroll
        for (int jl = 0; jl < 4; jl++) {
            float s = sc[jl][i];
            acc[jl].x += s * v.x;
            acc[jl].y += s * v.y;
            acc[jl].z += s * v.z;
            acc[jl].w += s * v.w;
        }
    }

#pragma unroll
    for (int jl = 0; jl < 4; jl++) {
        int j = j0 + jl;
        float4 sp4 = *(const float4*)(g_sp + (size_t)j * C2 + d);
        float4 o4;
        o4.x = silu_f(acc[jl].x * sp4.x);
        o4.y = silu_f(acc[jl].y * sp4.y);
        o4.z = silu_f(acc[jl].z * sp4.z);
        o4.w = silu_f(acc[jl].w * sp4.w);
        *(float4*)(out + ((size_t)(b * T2 + j)) * C2 + d) = o4;
    }
}

// ---------------------------------------------------------------------------
extern "C" void kernel_launch(void* const* d_in, const int* in_sizes, int n_in,
                              void* d_out, int out_size) {
    const float* values  = (const float*)d_in[0];
    const float* symbols = (const float*)d_in[1];
    const float* c1w     = (const float*)d_in[2];
    const float* c1b     = (const float*)d_in[3];
    const float* l1g     = (const float*)d_in[4];
    const float* l1b     = (const float*)d_in[5];
    const float* c2w     = (const float*)d_in[6];
    const float* c2b     = (const float*)d_in[7];
    const float* l2g     = (const float*)d_in[8];
    const float* l2b     = (const float*)d_in[9];
    float* out = (float*)d_out;
    float* out_vp = out + (size_t)BATCH * T2 * C2;   // second tuple element

    conv1_ln_silu<<<400, 128>>>(values, symbols, c1w, c1b, l1g, l1b);
    conv2_ln_silu<<<160, 256>>>(c2w, c2b, l2g, l2b, out_vp);
    sim_kernel<<<64, 256>>>();
    attn_kernel<<<128, 256>>>(out);
}

// round 2
// speedup vs baseline: 1.2563x; 1.2563x over previous
#include <cuda_runtime.h>
#include <math.h>

#define BATCH 4
#define T_IN 1920
#define E_IN 512
#define C1 128
#define T1 640
#define C2 1024
#define T2 128

// Scratch (device globals; no allocations allowed)
__device__ float g_h1[5 * T1 * C1];          // conv1 output: slots 0..3 = batches, 4 = symbols
__device__ float g_vp[BATCH * T2 * C2];      // values_projected
__device__ float g_sp[T2 * C2];              // symbol_projected
__device__ float g_S[BATCH * T2 * T2];       // similarity S[b][j][i]

__device__ __forceinline__ float silu_f(float y) { return y / (1.0f + expf(-y)); }

// ---- packed f32x2 helpers (ptxas never emits FFMA2 from C++) ----
__device__ __forceinline__ unsigned long long pk2(float lo, float hi) {
    unsigned long long r;
    asm("mov.b64 %0, {%1, %2};" : "=l"(r)
        : "r"(__float_as_uint(lo)), "r"(__float_as_uint(hi)));
    return r;
}
__device__ __forceinline__ unsigned long long fma2(unsigned long long a,
                                                   unsigned long long b,
                                                   unsigned long long c) {
    unsigned long long d;
    asm("fma.rn.f32x2 %0, %1, %2, %3;" : "=l"(d) : "l"(a), "l"(b), "l"(c));
    return d;
}
__device__ __forceinline__ float pksum(unsigned long long p) {
    unsigned int lo, hi;
    asm("mov.b64 {%0, %1}, %2;" : "=r"(lo), "=r"(hi) : "l"(p));
    return __uint_as_float(lo) + __uint_as_float(hi);
}

// ---------------------------------------------------------------------------
// Kernel A: conv1 (stride 3, window 5, pad 1/1) + layernorm(128) + silu
// 200 blocks x 256 threads. 16 timesteps/block.
// warp w owns timesteps {2w, 2w+1}; lane owns 4 channels. LN is warp-local.
// ---------------------------------------------------------------------------
#define TS1 16
#define ECH1 128
#define ROWS1 (3 * (TS1 - 1) + 5)   // 50

__global__ void conv1_ln_silu(const float* __restrict__ values,
                              const float* __restrict__ symbols,
                              const float* __restrict__ w,
                              const float* __restrict__ bias,
                              const float* __restrict__ lng,
                              const float* __restrict__ lnb) {
    __shared__ float xs[ROWS1 * ECH1];   // 25.6KB

    int blk = blockIdx.x;
    int src, t0;
    if (blk < 160) { src = blk / 40; t0 = (blk % 40) * TS1; }
    else           { src = 4;        t0 = (blk - 160) * TS1; }
    const float* x = (src < 4) ? (values + (size_t)src * T_IN * E_IN) : symbols;

    int base_row = t0 * 3 - 1;
    int t    = threadIdx.x;
    int lane = t & 31;
    int wrp  = t >> 5;          // 0..7
    int ch0  = lane * 4;        // 4 channels per lane
    int j0   = wrp * 2;         // 2 timesteps per warp

    unsigned long long acc2[2][4];
#pragma unroll
    for (int q = 0; q < 4; q++) {
        unsigned long long b0 = pk2(bias[ch0 + q], 0.f);
        acc2[0][q] = b0;
        acc2[1][q] = pk2(0.f, 0.f);
    }

    for (int cc = 0; cc < E_IN; cc += ECH1) {
        __syncthreads();
        for (int idx = t; idx < ROWS1 * (ECH1 / 4); idx += 256) {
            int r  = idx / (ECH1 / 4);
            int c4 = idx % (ECH1 / 4);
            int gr = base_row + r;
            float4 v = make_float4(0.f, 0.f, 0.f, 0.f);
            if (gr >= 0 && gr < T_IN)
                v = ((const float4*)(x + (size_t)gr * E_IN + cc))[c4];
            ((float4*)xs)[idx] = v;
        }
        __syncthreads();

#pragma unroll
        for (int k = 0; k < 5; k++) {
            for (int c = 0; c < ECH1; c += 4) {
                const float* wp = w + ((size_t)(k * E_IN + cc + c)) * C1 + ch0;
                float4 w0 = *(const float4*)(wp);
                float4 w1 = *(const float4*)(wp + C1);
                float4 w2 = *(const float4*)(wp + 2 * C1);
                float4 w3 = *(const float4*)(wp + 3 * C1);
                unsigned long long wa[4], wb[4];
                wa[0] = pk2(w0.x, w1.x); wa[1] = pk2(w0.y, w1.y);
                wa[2] = pk2(w0.z, w1.z); wa[3] = pk2(w0.w, w1.w);
                wb[0] = pk2(w2.x, w3.x); wb[1] = pk2(w2.y, w3.y);
                wb[2] = pk2(w2.z, w3.z); wb[3] = pk2(w2.w, w3.w);
#pragma unroll
                for (int jj = 0; jj < 2; jj++) {
                    const float4 xv = *(const float4*)&xs[(3 * (j0 + jj) + k) * ECH1 + c];
                    unsigned long long xa = pk2(xv.x, xv.y);
                    unsigned long long xb = pk2(xv.z, xv.w);
#pragma unroll
                    for (int q = 0; q < 4; q++) {
                        acc2[jj][q] = fma2(xa, wa[q], acc2[jj][q]);
                        acc2[jj][q] = fma2(xb, wb[q], acc2[jj][q]);
                    }
                }
            }
        }
    }

    // warp-local layernorm over 128 channels (32 lanes x 4 ch) + silu
    float gg[4], bb[4];
#pragma unroll
    for (int q = 0; q < 4; q++) { gg[q] = lng[ch0 + q]; bb[q] = lnb[ch0 + q]; }

#pragma unroll
    for (int jj = 0; jj < 2; jj++) {
        float v[4], s = 0.f, s2 = 0.f;
#pragma unroll
        for (int q = 0; q < 4; q++) {
            v[q] = pksum(acc2[jj][q]);
            if (jj == 1) v[q] += (q == 0 ? 0.f : 0.f);   // no-op, keep structure
            s += v[q]; s2 += v[q] * v[q];
        }
        // bias for jj==1 was packed into acc2[0] only for jj==0; fix: add bias now
        // (acc2[1] was initialized to 0; bias added below)
        if (jj == 1) {
#pragma unroll
            for (int q = 0; q < 4; q++) { s -= v[q]; s2 -= v[q] * v[q];
                v[q] += bias[ch0 + q]; s += v[q]; s2 += v[q] * v[q]; }
        }
#pragma unroll
        for (int off = 16; off; off >>= 1) {
            s  += __shfl_xor_sync(0xffffffffu, s,  off);
            s2 += __shfl_xor_sync(0xffffffffu, s2, off);
        }
        float m   = s * (1.0f / C1);
        float var = s2 * (1.0f / C1) - m * m;
        float rs  = rsqrtf(var + 1e-3f);
        float4 o4;
        o4.x = silu_f((v[0] - m) * rs * gg[0] + bb[0]);
        o4.y = silu_f((v[1] - m) * rs * gg[1] + bb[1]);
        o4.z = silu_f((v[2] - m) * rs * gg[2] + bb[2]);
        o4.w = silu_f((v[3] - m) * rs * gg[3] + bb[3]);
        *(float4*)&g_h1[((size_t)src * T1 + (t0 + j0 + jj)) * C1 + ch0] = o4;
    }
}

// ---------------------------------------------------------------------------
// Kernel B: conv2 (stride 5, window 3, no pad) + layernorm(1024) + silu
// 80 blocks x 256 threads. 8 timesteps/block; thread owns 4 adjacent channels.
// ---------------------------------------------------------------------------
#define TS2 8
#define ROWS2 (5 * (TS2 - 1) + 3)   // 38

__global__ void conv2_ln_silu(const float* __restrict__ w,
                              const float* __restrict__ bias,
                              const float* __restrict__ lng,
                              const float* __restrict__ lnb,
                              float* __restrict__ out_vp_copy) {
    __shared__ float xs[ROWS2 * C1];   // 19KB
    __shared__ float red[2][8];

    int blk = blockIdx.x;
    int src = blk / 16;
    int t0  = (blk % 16) * TS2;
    const float* x = g_h1 + (size_t)src * T1 * C1;
    int base_row = t0 * 5;

    int t   = threadIdx.x;
    int ch0 = t * 4;    // channels ch0..ch0+3

    for (int idx = t; idx < ROWS2 * (C1 / 4); idx += 256) {
        int r = idx / (C1 / 4), c4 = idx % (C1 / 4);
        ((float4*)xs)[idx] = ((const float4*)(x + (size_t)(base_row + r) * C1))[c4];
    }
    __syncthreads();

    unsigned long long acc2[TS2][4];
#pragma unroll
    for (int q = 0; q < 4; q++) acc2[0][q] = pk2(bias[ch0 + q], 0.f);
#pragma unroll
    for (int j = 1; j < TS2; j++)
#pragma unroll
        for (int q = 0; q < 4; q++) acc2[j][q] = pk2(0.f, 0.f);

#pragma unroll
    for (int k = 0; k < 3; k++) {
        for (int c = 0; c < C1; c += 2) {
            const float* wp = w + ((size_t)(k * C1 + c)) * C2 + ch0;
            float4 w0 = *(const float4*)(wp);
            float4 w1 = *(const float4*)(wp + C2);
            unsigned long long wpair[4];
            wpair[0] = pk2(w0.x, w1.x); wpair[1] = pk2(w0.y, w1.y);
            wpair[2] = pk2(w0.z, w1.z); wpair[3] = pk2(w0.w, w1.w);
#pragma unroll
            for (int j = 0; j < TS2; j++) {
                const float2 xv = *(const float2*)&xs[(5 * j + k) * C1 + c];
                unsigned long long xa = pk2(xv.x, xv.y);
#pragma unroll
                for (int q = 0; q < 4; q++)
                    acc2[j][q] = fma2(xa, wpair[q], acc2[j][q]);
            }
        }
    }

    int lane = t & 31, wid = t >> 5;
    float bsum[4];
#pragma unroll
    for (int q = 0; q < 4; q++) bsum[q] = bias[ch0 + q];
    float gg[4], bb[4];
#pragma unroll
    for (int q = 0; q < 4; q++) { gg[q] = lng[ch0 + q]; bb[q] = lnb[ch0 + q]; }

    for (int j = 0; j < TS2; j++) {
        float v[4], s = 0.f, s2 = 0.f;
#pragma unroll
        for (int q = 0; q < 4; q++) {
            v[q] = pksum(acc2[j][q]);
            if (j > 0) v[q] += bsum[q];    // bias packed only into j==0
            s += v[q]; s2 += v[q] * v[q];
        }
#pragma unroll
        for (int off = 16; off; off >>= 1) {
            s  += __shfl_xor_sync(0xffffffffu, s,  off);
            s2 += __shfl_xor_sync(0xffffffffu, s2, off);
        }
        if (lane == 0) { red[0][wid] = s; red[1][wid] = s2; }
        __syncthreads();
        float sum = 0.f, sumsq = 0.f;
#pragma unroll
        for (int q = 0; q < 8; q++) { sum += red[0][q]; sumsq += red[1][q]; }
        __syncthreads();
        float m   = sum * (1.0f / C2);
        float var = sumsq * (1.0f / C2) - m * m;
        float rs  = rsqrtf(var + 1e-3f);
        float4 o4;
        o4.x = silu_f((v[0] - m) * rs * gg[0] + bb[0]);
        o4.y = silu_f((v[1] - m) * rs * gg[1] + bb[1]);
        o4.z = silu_f((v[2] - m) * rs * gg[2] + bb[2]);
        o4.w = silu_f((v[3] - m) * rs * gg[3] + bb[3]);
        if (src < 4) {
            size_t idx = ((size_t)(src * T2 + t0 + j)) * C2 + ch0;
            *(float4*)&g_vp[idx] = o4;
            *(float4*)&out_vp_copy[idx] = o4;
        } else {
            *(float4*)&g_sp[(size_t)(t0 + j) * C2 + ch0] = o4;
        }
    }
}

// ---------------------------------------------------------------------------
// Kernel C: S[b,j,i] = mean_d sign(vp[b,i,d]) * sign(vp[b,i,d] + sp[j,d])
// 256 blocks (b, 8x8 tiles of 16x16) x 256 threads; 1 output per thread.
// sign product via sign-bit XOR (branch-free, 4 ops/elem).
// ---------------------------------------------------------------------------
__device__ __forceinline__ float sgnx(float a, float s) {
    float b = a + s;
    unsigned int x = (__float_as_uint(a) ^ __float_as_uint(b));
    return __uint_as_float((x & 0x80000000u) | 0x3f800000u);
}

__global__ void sim_kernel() {
    __shared__ float vps[16][132];
    __shared__ float sps[16][132];

    int blk = blockIdx.x;
    int b  = blk >> 6;
    int jt = (blk >> 3) & 7;
    int it = blk & 7;
    int i0 = it * 16, j0 = jt * 16;
    int t  = threadIdx.x;
    int ti = t & 15;
    int tj = t >> 4;

    float acc = 0.f;

    for (int d0 = 0; d0 < C2; d0 += 128) {
        __syncthreads();
        for (int e = t; e < 16 * 32; e += 256) {
            int r = e >> 5, c4 = e & 31;
            *(float4*)&vps[r][c4 * 4] =
                *(const float4*)&g_vp[((size_t)(b * T2 + i0 + r)) * C2 + d0 + c4 * 4];
            *(float4*)&sps[r][c4 * 4] =
                *(const float4*)&g_sp[(size_t)(j0 + r) * C2 + d0 + c4 * 4];
        }
        __syncthreads();
#pragma unroll 8
        for (int c4 = 0; c4 < 32; c4++) {
            float4 v = *(const float4*)&vps[ti][c4 * 4];
            float4 s = *(const float4*)&sps[tj][c4 * 4];
            acc += sgnx(v.x, s.x);
            acc += sgnx(v.y, s.y);
            acc += sgnx(v.z, s.z);
            acc += sgnx(v.w, s.w);
        }
    }

    g_S[((size_t)(b * T2 + (j0 + tj))) * T2 + (i0 + ti)] = acc * (1.0f / 1024.0f);
}

// ---------------------------------------------------------------------------
// Kernel D: softmax over i + attn = scores @ vp + O = silu(attn * sp)
// 256 blocks (b, j-group of 8, d-quarter of 256) x 128 threads (float2 each).
// ---------------------------------------------------------------------------
__global__ void attn_kernel(float* __restrict__ out) {
    __shared__ float sc[8][T2];

    int blk = blockIdx.x;
    int b  = blk >> 6;
    int jg = (blk >> 2) & 15;
    int dq = blk & 3;
    int j0 = jg * 8;
    int d0 = dq * 256;

    int t = threadIdx.x, lane = t & 31, wrp = t >> 5;

    // softmax: 4 warps x 2 rows each (redundant across d-quarters, cheap)
#pragma unroll
    for (int rr = 0; rr < 2; rr++) {
        int jl = wrp * 2 + rr;
        const float* Sr = g_S + ((size_t)b * T2 + (j0 + jl)) * T2;
        float v[4];
#pragma unroll
        for (int u = 0; u < 4; u++) v[u] = Sr[lane + 32 * u];
        float mx = fmaxf(fmaxf(v[0], v[1]), fmaxf(v[2], v[3]));
#pragma unroll
        for (int off = 16; off; off >>= 1)
            mx = fmaxf(mx, __shfl_xor_sync(0xffffffffu, mx, off));
        float sum = 0.f;
#pragma unroll
        for (int u = 0; u < 4; u++) { v[u] = expf(v[u] - mx); sum += v[u]; }
#pragma unroll
        for (int off = 16; off; off >>= 1)
            sum += __shfl_xor_sync(0xffffffffu, sum, off);
        float invs = 1.0f / sum;
#pragma unroll
        for (int u = 0; u < 4; u++) sc[jl][lane + 32 * u] = v[u] * invs;
    }
    __syncthreads();

    int d = d0 + 2 * t;
    float2 acc[8];
#pragma unroll
    for (int jl = 0; jl < 8; jl++) acc[jl] = make_float2(0.f, 0.f);

    const float* vpb = g_vp + (size_t)b * T2 * C2 + d;
#pragma unroll 2
    for (int i = 0; i < T2; i++) {
        float2 v = *(const float2*)(vpb + (size_t)i * C2);
#pragma unroll
        for (int jl = 0; jl < 8; jl++) {
            float s = sc[jl][i];
            acc[jl].x += s * v.x;
            acc[jl].y += s * v.y;
        }
    }

#pragma unroll
    for (int jl = 0; jl < 8; jl++) {
        int j = j0 + jl;
        float2 sp2 = *(const float2*)(g_sp + (size_t)j * C2 + d);
        float2 o2;
        o2.x = silu_f(acc[jl].x * sp2.x);
        o2.y = silu_f(acc[jl].y * sp2.y);
        *(float2*)(out + ((size_t)(b * T2 + j)) * C2 + d) = o2;
    }
}

// ---------------------------------------------------------------------------
extern "C" void kernel_launch(void* const* d_in, const int* in_sizes, int n_in,
                              void* d_out, int out_size) {
    const float* values  = (const float*)d_in[0];
    const float* symbols = (const float*)d_in[1];
    const float* c1w     = (const float*)d_in[2];
    const float* c1b     = (const float*)d_in[3];
    const float* l1g     = (const float*)d_in[4];
    const float* l1b     = (const float*)d_in[5];
    const float* c2w     = (const float*)d_in[6];
    const float* c2b     = (const float*)d_in[7];
    const float* l2g     = (const float*)d_in[8];
    const float* l2b     = (const float*)d_in[9];
    float* out = (float*)d_out;
    float* out_vp = out + (size_t)BATCH * T2 * C2;

    conv1_ln_silu<<<200, 256>>>(values, symbols, c1w, c1b, l1g, l1b);
    conv2_ln_silu<<<80, 256>>>(c2w, c2b, l2g, l2b, out_vp);
    sim_kernel<<<256, 256>>>();
    attn_kernel<<<256, 128>>>(out);
}